// round 4
// baseline (speedup 1.0000x reference)
#include <cuda_runtime.h>
#include <cstdint>

#define N_NODES   100000
#define FDIM      64
#define MAX_E     1250000

// ---------------- scratch (static __device__, 16B-aligned via float4) -------
__device__ float4 g_xw4[(size_t)N_NODES * 16];   // per-layer x@W   (N x 64 f32)
__device__ float4 g_h4 [(size_t)N_NODES * 16];   // layer-1 result  (N x 64 f32)
__device__ float  g_deg[N_NODES];
__device__ float  g_dis[N_NODES];
__device__ int2   g_edges[MAX_E];                // packed clamped (src,dst)
__device__ int    g_is64;                        // edge_index dtype flag

// ---------------- dtype probe: int64 data has zero high words ----------------
__global__ void k_detect(const int* __restrict__ ei32) {
    if (threadIdx.x == 0) {
        int allz = 1;
        #pragma unroll
        for (int i = 0; i < 64; i++)
            if (ei32[2 * i + 1] != 0) { allz = 0; break; }
        g_is64 = allz;   // all 64 odd words zero -> int64 layout
    }
}

// ---------------- degree init ----------------
__global__ void k_init_deg(int n) {
    int i = blockIdx.x * blockDim.x + threadIdx.x;
    if (i < n) g_deg[i] = 1.0f;   // self-loop
}

// ---------------- edge prep: decode (int32 or int64), clamp, count degrees --
__global__ void k_prep(const int* __restrict__ ei32, int E, int n) {
    int e = blockIdx.x * blockDim.x + threadIdx.x;
    if (e < E) {
        int s, d;
        if (g_is64) {
            const long long* ei64 = (const long long*)ei32;
            s = (int)ei64[e];
            d = (int)ei64[(size_t)E + e];
        } else {
            s = ei32[e];
            d = ei32[(size_t)E + e];
        }
        s = s < 0 ? 0 : (s >= n ? n - 1 : s);   // clamp: crash-proof
        d = d < 0 ? 0 : (d >= n ? n - 1 : d);
        g_edges[e] = make_int2(s, d);
        atomicAdd(&g_deg[d], 1.0f);
    }
}

// ---------------- dis = rsqrt(deg) ----------------
__global__ void k_dis(int n) {
    int i = blockIdx.x * blockDim.x + threadIdx.x;
    if (i < n) g_dis[i] = rsqrtf(g_deg[i]);
}

// ---------------- GEMM: xw = (relu?)(in) @ W ; acc = dis^2*xw + b ----------
__global__ __launch_bounds__(128) void k_gemm(
    const float* __restrict__ in_ext, int in_is_h,
    const float* __restrict__ W, const float* __restrict__ b,
    int relu, int n,
    float* __restrict__ acc_ext, int acc_is_h)
{
    const float* in  = in_is_h  ? (const float*)g_h4 : in_ext;
    float*       acc = acc_is_h ? (float*)g_h4       : acc_ext;
    float*       xw  = (float*)g_xw4;

    __shared__ float sW[64 * 64];
    __shared__ float sx[64][66];

    const int tid  = threadIdx.x;
    const int row0 = blockIdx.x * 64;

    for (int i = tid; i < 64 * 64; i += 128) sW[i] = W[i];
    for (int i = tid; i < 64 * 64; i += 128) {
        int r = i >> 6, c = i & 63;
        int gr = row0 + r;
        float v = (gr < n) ? in[(size_t)gr * 64 + c] : 0.0f;
        if (relu) v = fmaxf(v, 0.0f);
        sx[r][c] = v;
    }
    __syncthreads();

    const int tx = tid & 7;        // col group (8 cols each)
    const int ty = tid >> 3;       // row group (4 rows each)
    const int c0 = tx * 8;
    const int r0 = ty * 4;

    float a[4][8];
    #pragma unroll
    for (int i = 0; i < 4; i++)
        #pragma unroll
        for (int j = 0; j < 8; j++) a[i][j] = 0.0f;

    #pragma unroll 8
    for (int k = 0; k < 64; k++) {
        float4 w0 = *(const float4*)&sW[k * 64 + c0];
        float4 w1 = *(const float4*)&sW[k * 64 + c0 + 4];
        float wv[8] = {w0.x, w0.y, w0.z, w0.w, w1.x, w1.y, w1.z, w1.w};
        float xv[4];
        #pragma unroll
        for (int i = 0; i < 4; i++) xv[i] = sx[r0 + i][k];
        #pragma unroll
        for (int i = 0; i < 4; i++)
            #pragma unroll
            for (int j = 0; j < 8; j++)
                a[i][j] = fmaf(xv[i], wv[j], a[i][j]);
    }

    float4 bb0 = *(const float4*)&b[c0];
    float4 bb1 = *(const float4*)&b[c0 + 4];

    #pragma unroll
    for (int i = 0; i < 4; i++) {
        int gr = row0 + r0 + i;
        if (gr < n) {
            float dv = g_dis[gr];
            float s  = dv * dv;
            float4 v0 = make_float4(a[i][0], a[i][1], a[i][2], a[i][3]);
            float4 v1 = make_float4(a[i][4], a[i][5], a[i][6], a[i][7]);
            *(float4*)&xw[(size_t)gr * 64 + c0]     = v0;
            *(float4*)&xw[(size_t)gr * 64 + c0 + 4] = v1;
            float4 o0 = make_float4(s * v0.x + bb0.x, s * v0.y + bb0.y,
                                    s * v0.z + bb0.z, s * v0.w + bb0.w);
            float4 o1 = make_float4(s * v1.x + bb1.x, s * v1.y + bb1.y,
                                    s * v1.z + bb1.z, s * v1.w + bb1.w);
            *(float4*)&acc[(size_t)gr * 64 + c0]     = o0;
            *(float4*)&acc[(size_t)gr * 64 + c0 + 4] = o1;
        }
    }
}

// ---------------- edge scatter: out[d] += dis[s]*dis[d] * xw[s] ------------
// 16 threads per edge, one float4 each; vector red.global.add.v4.f32
__global__ __launch_bounds__(256) void k_scatter(
    float* __restrict__ out_ext, int out_is_h, int E)
{
    const float4* xw  = g_xw4;
    float4*       out = out_is_h ? g_h4 : (float4*)out_ext;

    int idx = blockIdx.x * blockDim.x + threadIdx.x;
    int e = idx >> 4;
    int q = idx & 15;
    if (e >= E) return;
    int2 ed  = g_edges[e];
    float nm = g_dis[ed.x] * g_dis[ed.y];
    float4 v = xw[(size_t)ed.x * 16 + q];
    float4* p = out + (size_t)ed.y * 16 + q;
    asm volatile("red.global.add.v4.f32 [%0], {%1,%2,%3,%4};"
                 :: "l"(p), "f"(nm * v.x), "f"(nm * v.y),
                    "f"(nm * v.z), "f"(nm * v.w)
                 : "memory");
}

// ---------------- launch ----------------
extern "C" void kernel_launch(void* const* d_in, const int* in_sizes, int n_in,
                              void* d_out, int out_size)
{
    // ---- identify inputs by element count (robust to metadata ordering) ----
    int ix = -1, iei = -1, iw1 = -1, iw2 = -1, ib1 = -1, ib2 = -1;
    for (int i = 0; i < n_in; i++) {
        int s = in_sizes[i];
        if      (s == N_NODES * FDIM) { if (ix  < 0) ix  = i; }
        else if (s == 2 * MAX_E)      { if (iei < 0) iei = i; }
        else if (s == FDIM * FDIM)    { if (iw1 < 0) iw1 = i; else if (iw2 < 0) iw2 = i; }
        else if (s == FDIM)           { if (ib1 < 0) ib1 = i; else if (ib2 < 0) ib2 = i; }
    }
    if (ix < 0 || iei < 0 || iw1 < 0 || iw2 < 0 || ib1 < 0 || ib2 < 0) {
        ix = 0; iei = 1; iw1 = 2; ib1 = 3; iw2 = 4; ib2 = 5;
    }

    const float* x   = (const float*)d_in[ix];
    const int*   ei  = (const int*)d_in[iei];    // int32 per harness contract
    const float* W1  = (const float*)d_in[iw1];
    const float* b1  = (const float*)d_in[ib1];
    const float* W2  = (const float*)d_in[iw2];
    const float* b2  = (const float*)d_in[ib2];
    float*       out = (float*)d_out;

    int n = in_sizes[ix] / FDIM;      // 100000
    int E = in_sizes[iei] / 2;        // 1250000
    if (n > N_NODES) n = N_NODES;
    if (E > MAX_E)   E = MAX_E;

    const int TB = 256;
    const int nodeBlocks  = (n + TB - 1) / TB;
    const int edgeBlocks  = (E + TB - 1) / TB;
    const int gemmBlocks  = (n + 63) / 64;
    const long long scTot = (long long)E * 16;
    const int scBlocks    = (int)((scTot + TB - 1) / TB);

    k_detect  <<<1, 32>>>(ei);
    k_init_deg<<<nodeBlocks, TB>>>(n);
    k_prep    <<<edgeBlocks, TB>>>(ei, E, n);
    k_dis     <<<nodeBlocks, TB>>>(n);

    // layer 1:  h = dis^2*(x@W1) + b1, then scatter-add edges into h
    k_gemm    <<<gemmBlocks, 128>>>(x, 0, W1, b1, /*relu=*/0, n, nullptr, 1);
    k_scatter <<<scBlocks, TB>>>(nullptr, 1, E);

    // layer 2:  out = dis^2*(relu(h)@W2) + b2, then scatter-add edges into out
    k_gemm    <<<gemmBlocks, 128>>>(nullptr, 1, W2, b2, /*relu=*/1, n, out, 0);
    k_scatter <<<scBlocks, TB>>>(out, 0, E);
}

// round 5
// speedup vs baseline: 1.1372x; 1.1372x over previous
#include <cuda_runtime.h>
#include <cstdint>

#define N_NODES   100000
#define FDIM      64
#define MAX_E     1250000
#define SCAN_BLK  1024                 // elements per scan block (256 thr x 4)
#define MAX_SB    128                  // max scan blocks (98 used)

// ---------------- scratch (static __device__) ----------------
__device__ float4 g_xw4[(size_t)N_NODES * 16];   // per-layer x@W (N x 64 f32)
__device__ float4 g_h4 [(size_t)N_NODES * 16];   // layer-1 result
__device__ float  g_dis[N_NODES];
__device__ int    g_cnt[N_NODES];                // in-degree histogram
__device__ int    g_rowstart[N_NODES + 1];       // CSR row offsets
__device__ int    g_cursor[N_NODES];             // fill cursors
__device__ int    g_csr[MAX_E];                  // CSR src indices
__device__ int2   g_edges[MAX_E];                // decoded (src,dst)
__device__ int    g_blocksum[MAX_SB];
__device__ int    g_blockbase[MAX_SB];
__device__ int    g_is64;

// ---------------- dtype probe: int64 data has zero high words --------------
__global__ void k_detect(const int* __restrict__ ei32) {
    if (threadIdx.x == 0) {
        int allz = 1;
        #pragma unroll
        for (int i = 0; i < 64; i++)
            if (ei32[2 * i + 1] != 0) { allz = 0; break; }
        g_is64 = allz;
    }
}

// ---------------- zero histogram ----------------
__global__ void k_zero(int n) {
    int i = blockIdx.x * blockDim.x + threadIdx.x;
    if (i < n) g_cnt[i] = 0;
}

// ---------------- edge decode + clamp + histogram ----------------
__global__ void k_prep(const int* __restrict__ ei32, int E, int n) {
    int e = blockIdx.x * blockDim.x + threadIdx.x;
    if (e < E) {
        int s, d;
        if (g_is64) {
            const long long* ei64 = (const long long*)ei32;
            s = (int)ei64[e];
            d = (int)ei64[(size_t)E + e];
        } else {
            s = ei32[e];
            d = ei32[(size_t)E + e];
        }
        s = s < 0 ? 0 : (s >= n ? n - 1 : s);
        d = d < 0 ? 0 : (d >= n ? n - 1 : d);
        g_edges[e] = make_int2(s, d);
        atomicAdd(&g_cnt[d], 1);
    }
}

// ---------------- scan phase 1: per-block sums + dis = rsqrt(cnt+1) --------
__global__ __launch_bounds__(256) void k_scan_block(int n) {
    __shared__ int ssum[256];
    int t   = threadIdx.x;
    int i0  = blockIdx.x * SCAN_BLK + t * 4;
    int sum = 0;
    #pragma unroll
    for (int k = 0; k < 4; k++) {
        int i = i0 + k;
        if (i < n) {
            int c = g_cnt[i];
            sum += c;
            g_dis[i] = rsqrtf((float)c + 1.0f);   // +1 self-loop
        }
    }
    ssum[t] = sum;
    __syncthreads();
    // block reduction
    for (int off = 128; off > 0; off >>= 1) {
        if (t < off) ssum[t] += ssum[t + off];
        __syncthreads();
    }
    if (t == 0) g_blocksum[blockIdx.x] = ssum[0];
}

// ---------------- scan phase 2: exclusive scan of block sums ---------------
__global__ __launch_bounds__(128) void k_scan_top(int nb, int n, int E) {
    __shared__ int s[128];
    int t = threadIdx.x;
    int v = (t < nb) ? g_blocksum[t] : 0;
    s[t] = v;
    __syncthreads();
    for (int off = 1; off < 128; off <<= 1) {
        int a = (t >= off) ? s[t - off] : 0;
        __syncthreads();
        s[t] += a;
        __syncthreads();
    }
    if (t < nb) g_blockbase[t] = s[t] - v;   // exclusive
    if (t == 0) g_rowstart[n] = E;
}

// ---------------- scan phase 3: final offsets + cursors --------------------
__global__ __launch_bounds__(256) void k_scan_fin(int n) {
    __shared__ int s[256];
    int t  = threadIdx.x;
    int i0 = blockIdx.x * SCAN_BLK + t * 4;
    int c[4];
    int sum = 0;
    #pragma unroll
    for (int k = 0; k < 4; k++) {
        int i = i0 + k;
        c[k] = (i < n) ? g_cnt[i] : 0;
        sum += c[k];
    }
    int own = sum;
    s[t] = sum;
    __syncthreads();
    for (int off = 1; off < 256; off <<= 1) {
        int a = (t >= off) ? s[t - off] : 0;
        __syncthreads();
        s[t] += a;
        __syncthreads();
    }
    int base = g_blockbase[blockIdx.x] + s[t] - own;   // exclusive for thread
    #pragma unroll
    for (int k = 0; k < 4; k++) {
        int i = i0 + k;
        if (i < n) {
            g_rowstart[i] = base;
            g_cursor[i]   = base;
            base += c[k];
        }
    }
}

// ---------------- CSR fill ----------------
__global__ void k_fill(int E) {
    int e = blockIdx.x * blockDim.x + threadIdx.x;
    if (e < E) {
        int2 ed = g_edges[e];
        int pos = atomicAdd(&g_cursor[ed.y], 1);
        g_csr[pos] = ed.x;
    }
}

// ---------------- GEMM: xw = (relu?)(in) @ W ; acc = dis^2*xw + b ----------
__global__ __launch_bounds__(128) void k_gemm(
    const float* __restrict__ in_ext, int in_is_h,
    const float* __restrict__ W, const float* __restrict__ b,
    int relu, int n,
    float* __restrict__ acc_ext, int acc_is_h)
{
    const float* in  = in_is_h  ? (const float*)g_h4 : in_ext;
    float*       acc = acc_is_h ? (float*)g_h4       : acc_ext;
    float*       xw  = (float*)g_xw4;

    __shared__ float sW[64 * 64];
    __shared__ float sx[64][66];

    const int tid  = threadIdx.x;
    const int row0 = blockIdx.x * 64;

    for (int i = tid; i < 64 * 64; i += 128) sW[i] = W[i];
    for (int i = tid; i < 64 * 64; i += 128) {
        int r = i >> 6, c = i & 63;
        int gr = row0 + r;
        float v = (gr < n) ? in[(size_t)gr * 64 + c] : 0.0f;
        if (relu) v = fmaxf(v, 0.0f);
        sx[r][c] = v;
    }
    __syncthreads();

    const int tx = tid & 7;
    const int ty = tid >> 3;
    const int c0 = tx * 8;
    const int r0 = ty * 4;

    float a[4][8];
    #pragma unroll
    for (int i = 0; i < 4; i++)
        #pragma unroll
        for (int j = 0; j < 8; j++) a[i][j] = 0.0f;

    #pragma unroll 8
    for (int k = 0; k < 64; k++) {
        float4 w0 = *(const float4*)&sW[k * 64 + c0];
        float4 w1 = *(const float4*)&sW[k * 64 + c0 + 4];
        float wv[8] = {w0.x, w0.y, w0.z, w0.w, w1.x, w1.y, w1.z, w1.w};
        float xv[4];
        #pragma unroll
        for (int i = 0; i < 4; i++) xv[i] = sx[r0 + i][k];
        #pragma unroll
        for (int i = 0; i < 4; i++)
            #pragma unroll
            for (int j = 0; j < 8; j++)
                a[i][j] = fmaf(xv[i], wv[j], a[i][j]);
    }

    float4 bb0 = *(const float4*)&b[c0];
    float4 bb1 = *(const float4*)&b[c0 + 4];

    #pragma unroll
    for (int i = 0; i < 4; i++) {
        int gr = row0 + r0 + i;
        if (gr < n) {
            float dv = g_dis[gr];
            float s  = dv * dv;
            float4 v0 = make_float4(a[i][0], a[i][1], a[i][2], a[i][3]);
            float4 v1 = make_float4(a[i][4], a[i][5], a[i][6], a[i][7]);
            *(float4*)&xw[(size_t)gr * 64 + c0]     = v0;
            *(float4*)&xw[(size_t)gr * 64 + c0 + 4] = v1;
            float4 o0 = make_float4(s * v0.x + bb0.x, s * v0.y + bb0.y,
                                    s * v0.z + bb0.z, s * v0.w + bb0.w);
            float4 o1 = make_float4(s * v1.x + bb1.x, s * v1.y + bb1.y,
                                    s * v1.z + bb1.z, s * v1.w + bb1.w);
            *(float4*)&acc[(size_t)gr * 64 + c0]     = o0;
            *(float4*)&acc[(size_t)gr * 64 + c0 + 4] = o1;
        }
    }
}

// ---------------- CSR gather: out[d] += sum_j dis[s_j]*dis[d]*xw[s_j] ------
// warp per dst node; lanes 0-15 / 16-31 process alternating edges;
// 16 lanes span the 64-float row as float4s. No atomics.
__global__ __launch_bounds__(256) void k_gather(
    float* __restrict__ out_ext, int out_is_h, int n)
{
    const float4* xw  = g_xw4;
    float4*       out = out_is_h ? g_h4 : (float4*)out_ext;

    int warp = (blockIdx.x * blockDim.x + threadIdx.x) >> 5;
    if (warp >= n) return;
    int lane = threadIdx.x & 31;
    int half = lane >> 4;
    int q    = lane & 15;

    int   rs   = g_rowstart[warp];
    int   re   = g_rowstart[warp + 1];
    float disd = g_dis[warp];

    size_t oidx = (size_t)warp * 16 + q;
    float4 o;
    if (half == 0) o = out[oidx];     // init = dis^2*xw + b (from GEMM)

    float4 acc = make_float4(0.f, 0.f, 0.f, 0.f);
    for (int j = rs + half; j < re; j += 2) {
        int   s  = g_csr[j];
        float nm = g_dis[s] * disd;
        float4 v = xw[(size_t)s * 16 + q];
        acc.x = fmaf(nm, v.x, acc.x);
        acc.y = fmaf(nm, v.y, acc.y);
        acc.z = fmaf(nm, v.z, acc.z);
        acc.w = fmaf(nm, v.w, acc.w);
    }
    // combine the two halves
    acc.x += __shfl_xor_sync(0xffffffffu, acc.x, 16);
    acc.y += __shfl_xor_sync(0xffffffffu, acc.y, 16);
    acc.z += __shfl_xor_sync(0xffffffffu, acc.z, 16);
    acc.w += __shfl_xor_sync(0xffffffffu, acc.w, 16);

    if (half == 0) {
        o.x += acc.x; o.y += acc.y; o.z += acc.z; o.w += acc.w;
        out[oidx] = o;
    }
}

// ---------------- launch ----------------
extern "C" void kernel_launch(void* const* d_in, const int* in_sizes, int n_in,
                              void* d_out, int out_size)
{
    // identify inputs by element count (robust to ordering)
    int ix = -1, iei = -1, iw1 = -1, iw2 = -1, ib1 = -1, ib2 = -1;
    for (int i = 0; i < n_in; i++) {
        int s = in_sizes[i];
        if      (s == N_NODES * FDIM) { if (ix  < 0) ix  = i; }
        else if (s == 2 * MAX_E)      { if (iei < 0) iei = i; }
        else if (s == FDIM * FDIM)    { if (iw1 < 0) iw1 = i; else if (iw2 < 0) iw2 = i; }
        else if (s == FDIM)           { if (ib1 < 0) ib1 = i; else if (ib2 < 0) ib2 = i; }
    }
    if (ix < 0 || iei < 0 || iw1 < 0 || iw2 < 0 || ib1 < 0 || ib2 < 0) {
        ix = 0; iei = 1; iw1 = 2; ib1 = 3; iw2 = 4; ib2 = 5;
    }

    const float* x   = (const float*)d_in[ix];
    const int*   ei  = (const int*)d_in[iei];
    const float* W1  = (const float*)d_in[iw1];
    const float* b1  = (const float*)d_in[ib1];
    const float* W2  = (const float*)d_in[iw2];
    const float* b2  = (const float*)d_in[ib2];
    float*       out = (float*)d_out;

    int n = in_sizes[ix] / FDIM;
    int E = in_sizes[iei] / 2;
    if (n > N_NODES) n = N_NODES;
    if (E > MAX_E)   E = MAX_E;

    const int TB = 256;
    const int nodeBlocks = (n + TB - 1) / TB;
    const int edgeBlocks = (E + TB - 1) / TB;
    const int gemmBlocks = (n + 63) / 64;
    const int nbScan     = (n + SCAN_BLK - 1) / SCAN_BLK;       // 98
    const int gthBlocks  = (n + 7) / 8;                          // 8 warps/block

    k_detect    <<<1, 32>>>(ei);
    k_zero      <<<nodeBlocks, TB>>>(n);
    k_prep      <<<edgeBlocks, TB>>>(ei, E, n);
    k_scan_block<<<nbScan, 256>>>(n);
    k_scan_top  <<<1, 128>>>(nbScan, n, E);
    k_scan_fin  <<<nbScan, 256>>>(n);
    k_fill      <<<edgeBlocks, TB>>>(E);

    // layer 1: h = dis^2*(x@W1) + b1  (+= neighbor messages)
    k_gemm  <<<gemmBlocks, 128>>>(x, 0, W1, b1, /*relu=*/0, n, nullptr, 1);
    k_gather<<<gthBlocks, TB>>>(nullptr, 1, n);

    // layer 2: out = dis^2*(relu(h)@W2) + b2  (+= neighbor messages)
    k_gemm  <<<gemmBlocks, 128>>>(nullptr, 1, W2, b2, /*relu=*/1, n, out, 0);
    k_gather<<<gthBlocks, TB>>>(out, 0, n);
}

// round 6
// speedup vs baseline: 1.2199x; 1.0728x over previous
#include <cuda_runtime.h>
#include <cstdint>

#define N_NODES   100000
#define FDIM      64
#define MAX_E     1250000
#define SCAN_BLK  1024                 // elements per scan block (256 thr x 4)
#define MAX_SB    128                  // max scan blocks (98 used)

// ---------------- scratch (static __device__) ----------------
__device__ float4 g_xw4[(size_t)N_NODES * 16];   // per-layer x@W (N x 64 f32)
__device__ float4 g_h4 [(size_t)N_NODES * 16];   // layer-1 result
__device__ float  g_dis[N_NODES];
__device__ int    g_cnt[N_NODES];                // in-degree histogram
__device__ int    g_rowstart[N_NODES + 1];       // CSR row offsets
__device__ int    g_cursor[N_NODES];             // fill cursors
__device__ int    g_csr[MAX_E];                  // CSR src indices
__device__ int    g_blocksum[MAX_SB];
__device__ int    g_blockbase[MAX_SB];
__device__ int    g_is64;

// ---------------- zero histogram + dtype probe (fused) ----------------
__global__ void k_zero(const int* __restrict__ ei32, int n) {
    int i = blockIdx.x * blockDim.x + threadIdx.x;
    if (i < n) g_cnt[i] = 0;
    if (i == 0) {
        int allz = 1;
        #pragma unroll
        for (int k = 0; k < 64; k++)
            if (ei32[2 * k + 1] != 0) { allz = 0; break; }
        g_is64 = allz;   // all odd words zero -> int64 layout
    }
}

// ---------------- histogram of dst (reads dst half only in int32 case) -----
__global__ void k_hist(const int* __restrict__ ei32, int E, int n) {
    int e = blockIdx.x * blockDim.x + threadIdx.x;
    if (e < E) {
        int d;
        if (g_is64) d = (int)((const long long*)ei32)[(size_t)E + e];
        else        d = ei32[(size_t)E + e];
        d = d < 0 ? 0 : (d >= n ? n - 1 : d);
        atomicAdd(&g_cnt[d], 1);
    }
}

// ---------------- scan phase 1: per-block sums + dis = rsqrt(cnt+1) --------
__global__ __launch_bounds__(256) void k_scan_block(int n) {
    __shared__ int ssum[256];
    int t   = threadIdx.x;
    int i0  = blockIdx.x * SCAN_BLK + t * 4;
    int sum = 0;
    #pragma unroll
    for (int k = 0; k < 4; k++) {
        int i = i0 + k;
        if (i < n) {
            int c = g_cnt[i];
            sum += c;
            g_dis[i] = rsqrtf((float)c + 1.0f);   // +1 self-loop
        }
    }
    ssum[t] = sum;
    __syncthreads();
    for (int off = 128; off > 0; off >>= 1) {
        if (t < off) ssum[t] += ssum[t + off];
        __syncthreads();
    }
    if (t == 0) g_blocksum[blockIdx.x] = ssum[0];
}

// ---------------- scan phase 2: exclusive scan of block sums ---------------
__global__ __launch_bounds__(128) void k_scan_top(int nb, int n, int E) {
    __shared__ int s[128];
    int t = threadIdx.x;
    int v = (t < nb) ? g_blocksum[t] : 0;
    s[t] = v;
    __syncthreads();
    for (int off = 1; off < 128; off <<= 1) {
        int a = (t >= off) ? s[t - off] : 0;
        __syncthreads();
        s[t] += a;
        __syncthreads();
    }
    if (t < nb) g_blockbase[t] = s[t] - v;
    if (t == 0) g_rowstart[n] = E;
}

// ---------------- scan phase 3: final offsets + cursors --------------------
__global__ __launch_bounds__(256) void k_scan_fin(int n) {
    __shared__ int s[256];
    int t  = threadIdx.x;
    int i0 = blockIdx.x * SCAN_BLK + t * 4;
    int c[4];
    int sum = 0;
    #pragma unroll
    for (int k = 0; k < 4; k++) {
        int i = i0 + k;
        c[k] = (i < n) ? g_cnt[i] : 0;
        sum += c[k];
    }
    int own = sum;
    s[t] = sum;
    __syncthreads();
    for (int off = 1; off < 256; off <<= 1) {
        int a = (t >= off) ? s[t - off] : 0;
        __syncthreads();
        s[t] += a;
        __syncthreads();
    }
    int base = g_blockbase[blockIdx.x] + s[t] - own;
    #pragma unroll
    for (int k = 0; k < 4; k++) {
        int i = i0 + k;
        if (i < n) {
            g_rowstart[i] = base;
            g_cursor[i]   = base;
            base += c[k];
        }
    }
}

// ---------------- CSR fill (decodes edge_index directly) -------------------
__global__ void k_fill(const int* __restrict__ ei32, int E, int n) {
    int e = blockIdx.x * blockDim.x + threadIdx.x;
    if (e < E) {
        int s, d;
        if (g_is64) {
            const long long* ei64 = (const long long*)ei32;
            s = (int)ei64[e];
            d = (int)ei64[(size_t)E + e];
        } else {
            s = ei32[e];
            d = ei32[(size_t)E + e];
        }
        s = s < 0 ? 0 : (s >= n ? n - 1 : s);
        d = d < 0 ? 0 : (d >= n ? n - 1 : d);
        int pos = atomicAdd(&g_cursor[d], 1);
        g_csr[pos] = s;
    }
}

// ---------------- GEMM (packed f32x2): xw=(relu?)(in)@W ; acc=dis^2*xw+b ---
__global__ __launch_bounds__(128) void k_gemm(
    const float* __restrict__ in_ext, int in_is_h,
    const float* __restrict__ W, const float* __restrict__ b,
    int relu, int n,
    float* __restrict__ acc_ext, int acc_is_h)
{
    const float* in  = in_is_h  ? (const float*)g_h4 : in_ext;
    float*       acc = acc_is_h ? (float*)g_h4       : acc_ext;
    float*       xw  = (float*)g_xw4;

    __shared__ float sW[64 * 64];
    __shared__ float sx[64][66];

    const int tid  = threadIdx.x;
    const int row0 = blockIdx.x * 64;

    for (int i = tid; i < 64 * 64; i += 128) sW[i] = W[i];
    for (int i = tid; i < 64 * 64; i += 128) {
        int r = i >> 6, c = i & 63;
        int gr = row0 + r;
        float v = (gr < n) ? in[(size_t)gr * 64 + c] : 0.0f;
        if (relu) v = fmaxf(v, 0.0f);
        sx[r][c] = v;
    }
    __syncthreads();

    const int tx = tid & 7;        // col group (8 cols = 4 pairs)
    const int ty = tid >> 3;       // row group (4 rows)
    const int c0 = tx * 8;
    const int r0 = ty * 4;

    unsigned long long a2[4][4];   // [row][colpair], each = packed 2 x f32
    #pragma unroll
    for (int i = 0; i < 4; i++)
        #pragma unroll
        for (int j = 0; j < 4; j++) a2[i][j] = 0ull;

    #pragma unroll 4
    for (int k = 0; k < 64; k++) {
        const unsigned long long* wp =
            (const unsigned long long*)&sW[k * 64 + c0];
        unsigned long long w0 = wp[0], w1 = wp[1], w2 = wp[2], w3 = wp[3];
        #pragma unroll
        for (int i = 0; i < 4; i++) {
            float xv = sx[r0 + i][k];
            unsigned long long xb;
            asm("mov.b64 %0, {%1,%1};" : "=l"(xb) : "f"(xv));
            asm("fma.rn.f32x2 %0, %1, %2, %0;" : "+l"(a2[i][0]) : "l"(xb), "l"(w0));
            asm("fma.rn.f32x2 %0, %1, %2, %0;" : "+l"(a2[i][1]) : "l"(xb), "l"(w1));
            asm("fma.rn.f32x2 %0, %1, %2, %0;" : "+l"(a2[i][2]) : "l"(xb), "l"(w2));
            asm("fma.rn.f32x2 %0, %1, %2, %0;" : "+l"(a2[i][3]) : "l"(xb), "l"(w3));
        }
    }

    float4 bb0 = *(const float4*)&b[c0];
    float4 bb1 = *(const float4*)&b[c0 + 4];

    #pragma unroll
    for (int i = 0; i < 4; i++) {
        int gr = row0 + r0 + i;
        if (gr < n) {
            float av[8];
            #pragma unroll
            for (int j = 0; j < 4; j++)
                asm("mov.b64 {%0,%1}, %2;"
                    : "=f"(av[2 * j]), "=f"(av[2 * j + 1]) : "l"(a2[i][j]));
            float dv = g_dis[gr];
            float s  = dv * dv;
            float4 v0 = make_float4(av[0], av[1], av[2], av[3]);
            float4 v1 = make_float4(av[4], av[5], av[6], av[7]);
            *(float4*)&xw[(size_t)gr * 64 + c0]     = v0;
            *(float4*)&xw[(size_t)gr * 64 + c0 + 4] = v1;
            float4 o0 = make_float4(s * v0.x + bb0.x, s * v0.y + bb0.y,
                                    s * v0.z + bb0.z, s * v0.w + bb0.w);
            float4 o1 = make_float4(s * v1.x + bb1.x, s * v1.y + bb1.y,
                                    s * v1.z + bb1.z, s * v1.w + bb1.w);
            *(float4*)&acc[(size_t)gr * 64 + c0]     = o0;
            *(float4*)&acc[(size_t)gr * 64 + c0 + 4] = o1;
        }
    }
}

// ---------------- CSR gather, 2-edge unrolled for MLP ----------------------
// warp per dst node; halves (16 lanes) process alternating edges; each lane
// owns one float4 of the 64-float row. No atomics.
__global__ __launch_bounds__(256) void k_gather(
    float* __restrict__ out_ext, int out_is_h, int n)
{
    const float4* xw  = g_xw4;
    float4*       out = out_is_h ? g_h4 : (float4*)out_ext;

    int warp = (blockIdx.x * blockDim.x + threadIdx.x) >> 5;
    if (warp >= n) return;
    int lane = threadIdx.x & 31;
    int half = lane >> 4;
    int q    = lane & 15;

    int   rs   = g_rowstart[warp];
    int   re   = g_rowstart[warp + 1];
    float disd = g_dis[warp];

    size_t oidx = (size_t)warp * 16 + q;
    float4 o;
    if (half == 0) o = out[oidx];     // init = dis^2*xw + b (from GEMM)

    float4 acc = make_float4(0.f, 0.f, 0.f, 0.f);
    int j = rs + half;
    // 2-edge unroll: issue both csr loads, then both dis+row loads (MLP=2)
    for (; j + 2 < re; j += 4) {
        int s0 = g_csr[j];
        int s1 = g_csr[j + 2];
        float n0 = g_dis[s0] * disd;
        float n1 = g_dis[s1] * disd;
        float4 v0 = xw[(size_t)s0 * 16 + q];
        float4 v1 = xw[(size_t)s1 * 16 + q];
        acc.x = fmaf(n0, v0.x, acc.x);
        acc.y = fmaf(n0, v0.y, acc.y);
        acc.z = fmaf(n0, v0.z, acc.z);
        acc.w = fmaf(n0, v0.w, acc.w);
        acc.x = fmaf(n1, v1.x, acc.x);
        acc.y = fmaf(n1, v1.y, acc.y);
        acc.z = fmaf(n1, v1.z, acc.z);
        acc.w = fmaf(n1, v1.w, acc.w);
    }
    if (j < re) {
        int   s  = g_csr[j];
        float nm = g_dis[s] * disd;
        float4 v = xw[(size_t)s * 16 + q];
        acc.x = fmaf(nm, v.x, acc.x);
        acc.y = fmaf(nm, v.y, acc.y);
        acc.z = fmaf(nm, v.z, acc.z);
        acc.w = fmaf(nm, v.w, acc.w);
    }
    acc.x += __shfl_xor_sync(0xffffffffu, acc.x, 16);
    acc.y += __shfl_xor_sync(0xffffffffu, acc.y, 16);
    acc.z += __shfl_xor_sync(0xffffffffu, acc.z, 16);
    acc.w += __shfl_xor_sync(0xffffffffu, acc.w, 16);

    if (half == 0) {
        o.x += acc.x; o.y += acc.y; o.z += acc.z; o.w += acc.w;
        out[oidx] = o;
    }
}

// ---------------- launch ----------------
extern "C" void kernel_launch(void* const* d_in, const int* in_sizes, int n_in,
                              void* d_out, int out_size)
{
    int ix = -1, iei = -1, iw1 = -1, iw2 = -1, ib1 = -1, ib2 = -1;
    for (int i = 0; i < n_in; i++) {
        int s = in_sizes[i];
        if      (s == N_NODES * FDIM) { if (ix  < 0) ix  = i; }
        else if (s == 2 * MAX_E)      { if (iei < 0) iei = i; }
        else if (s == FDIM * FDIM)    { if (iw1 < 0) iw1 = i; else if (iw2 < 0) iw2 = i; }
        else if (s == FDIM)           { if (ib1 < 0) ib1 = i; else if (ib2 < 0) ib2 = i; }
    }
    if (ix < 0 || iei < 0 || iw1 < 0 || iw2 < 0 || ib1 < 0 || ib2 < 0) {
        ix = 0; iei = 1; iw1 = 2; ib1 = 3; iw2 = 4; ib2 = 5;
    }

    const float* x   = (const float*)d_in[ix];
    const int*   ei  = (const int*)d_in[iei];
    const float* W1  = (const float*)d_in[iw1];
    const float* b1  = (const float*)d_in[ib1];
    const float* W2  = (const float*)d_in[iw2];
    const float* b2  = (const float*)d_in[ib2];
    float*       out = (float*)d_out;

    int n = in_sizes[ix] / FDIM;
    int E = in_sizes[iei] / 2;
    if (n > N_NODES) n = N_NODES;
    if (E > MAX_E)   E = MAX_E;

    const int TB = 256;
    const int nodeBlocks = (n + TB - 1) / TB;
    const int edgeBlocks = (E + TB - 1) / TB;
    const int gemmBlocks = (n + 63) / 64;
    const int nbScan     = (n + SCAN_BLK - 1) / SCAN_BLK;
    const int gthBlocks  = (n + 7) / 8;

    k_zero      <<<nodeBlocks, TB>>>(ei, n);
    k_hist      <<<edgeBlocks, TB>>>(ei, E, n);
    k_scan_block<<<nbScan, 256>>>(n);
    k_scan_top  <<<1, 128>>>(nbScan, n, E);
    k_scan_fin  <<<nbScan, 256>>>(n);
    k_fill      <<<edgeBlocks, TB>>>(ei, E, n);

    // layer 1: h = dis^2*(x@W1) + b1  (+= neighbor messages)
    k_gemm  <<<gemmBlocks, 128>>>(x, 0, W1, b1, /*relu=*/0, n, nullptr, 1);
    k_gather<<<gthBlocks, TB>>>(nullptr, 1, n);

    // layer 2: out = dis^2*(relu(h)@W2) + b2  (+= neighbor messages)
    k_gemm  <<<gemmBlocks, 128>>>(nullptr, 1, W2, b2, /*relu=*/1, n, out, 0);
    k_gather<<<gthBlocks, TB>>>(out, 0, n);
}

// round 7
// speedup vs baseline: 1.2567x; 1.0301x over previous
#include <cuda_runtime.h>
#include <cstdint>

#define N_NODES   100000
#define FDIM      64
#define MAX_E     1250000
#define SCAN_BLK  1024                 // elements per scan block (256 thr x 4)
#define MAX_SB    128                  // max scan blocks (98 used)

typedef unsigned long long ull;

// ---------------- scratch (static __device__) ----------------
__device__ float4 g_xw4[(size_t)N_NODES * 16];   // per-layer x@W (N x 64 f32)
__device__ float4 g_h4 [(size_t)N_NODES * 16];   // layer-1 result
__device__ float  g_dis[N_NODES];
__device__ int    g_cnt[N_NODES];                // in-degree histogram
__device__ int    g_rowstart[N_NODES + 1];       // CSR row offsets
__device__ int    g_cursor[N_NODES];             // fill cursors
__device__ int    g_csr[MAX_E];                  // CSR src indices
__device__ int    g_blocksum[MAX_SB];
__device__ int    g_is64;

// ---------------- zero histogram + dtype probe (fused) ----------------
__global__ void k_zero(const int* __restrict__ ei32, int n) {
    int i = blockIdx.x * blockDim.x + threadIdx.x;
    if (i < n) g_cnt[i] = 0;
    if (i == 0) {
        int allz = 1;
        #pragma unroll
        for (int k = 0; k < 64; k++)
            if (ei32[2 * k + 1] != 0) { allz = 0; break; }
        g_is64 = allz;   // all odd words zero -> int64 layout
    }
}

// ---------------- histogram of dst ----------------
__global__ void k_hist(const int* __restrict__ ei32, int E, int n) {
    int e = blockIdx.x * blockDim.x + threadIdx.x;
    if (e < E) {
        int d;
        if (g_is64) d = (int)((const long long*)ei32)[(size_t)E + e];
        else        d = ei32[(size_t)E + e];
        d = d < 0 ? 0 : (d >= n ? n - 1 : d);
        atomicAdd(&g_cnt[d], 1);
    }
}

// ---------------- scan phase 1: per-block sums + dis = rsqrt(cnt+1) --------
__global__ __launch_bounds__(256) void k_scan_block(int n) {
    __shared__ int ssum[256];
    int t   = threadIdx.x;
    int i0  = blockIdx.x * SCAN_BLK + t * 4;
    int sum = 0;
    #pragma unroll
    for (int k = 0; k < 4; k++) {
        int i = i0 + k;
        if (i < n) {
            int c = g_cnt[i];
            sum += c;
            g_dis[i] = rsqrtf((float)c + 1.0f);   // +1 self-loop
        }
    }
    ssum[t] = sum;
    __syncthreads();
    for (int off = 128; off > 0; off >>= 1) {
        if (t < off) ssum[t] += ssum[t + off];
        __syncthreads();
    }
    if (t == 0) g_blocksum[blockIdx.x] = ssum[0];
}

// ------ scan phase 2 (fused): redundant top scan + final offsets/cursors ---
__global__ __launch_bounds__(256) void k_scan_fin(int nb, int n, int E) {
    __shared__ int tops[MAX_SB];
    __shared__ int s[256];
    __shared__ int sbase;
    int t = threadIdx.x;

    // redundant 98-element top-level scan in every block
    if (t < MAX_SB) tops[t] = (t < nb) ? g_blocksum[t] : 0;
    __syncthreads();
    for (int off = 1; off < MAX_SB; off <<= 1) {
        int a = 0;
        if (t < MAX_SB && t >= off) a = tops[t - off];
        __syncthreads();
        if (t < MAX_SB) tops[t] += a;
        __syncthreads();
    }
    if (t == 0) {
        sbase = (blockIdx.x == 0) ? 0 : tops[blockIdx.x - 1];  // exclusive
        if (blockIdx.x == 0) g_rowstart[n] = E;
    }
    __syncthreads();

    int i0 = blockIdx.x * SCAN_BLK + t * 4;
    int c[4];
    int sum = 0;
    #pragma unroll
    for (int k = 0; k < 4; k++) {
        int i = i0 + k;
        c[k] = (i < n) ? g_cnt[i] : 0;
        sum += c[k];
    }
    int own = sum;
    s[t] = sum;
    __syncthreads();
    for (int off = 1; off < 256; off <<= 1) {
        int a = (t >= off) ? s[t - off] : 0;
        __syncthreads();
        s[t] += a;
        __syncthreads();
    }
    int base = sbase + s[t] - own;      // exclusive for this thread
    #pragma unroll
    for (int k = 0; k < 4; k++) {
        int i = i0 + k;
        if (i < n) {
            g_rowstart[i] = base;
            g_cursor[i]   = base;
            base += c[k];
        }
    }
}

// ---------------- CSR fill (decodes edge_index directly) -------------------
__global__ void k_fill(const int* __restrict__ ei32, int E, int n) {
    int e = blockIdx.x * blockDim.x + threadIdx.x;
    if (e < E) {
        int s, d;
        if (g_is64) {
            const long long* ei64 = (const long long*)ei32;
            s = (int)ei64[e];
            d = (int)ei64[(size_t)E + e];
        } else {
            s = ei32[e];
            d = ei32[(size_t)E + e];
        }
        s = s < 0 ? 0 : (s >= n ? n - 1 : s);
        d = d < 0 ? 0 : (d >= n ? n - 1 : d);
        int pos = atomicAdd(&g_cursor[d], 1);
        g_csr[pos] = s;
    }
}

// ---------------- GEMM (packed f32x2, k-paired) ----------------------------
__global__ __launch_bounds__(128) void k_gemm(
    const float* __restrict__ in_ext, int in_is_h,
    const float* __restrict__ W, const float* __restrict__ b,
    int relu, int n,
    float* __restrict__ acc_ext, int acc_is_h)
{
    const float* in  = in_is_h  ? (const float*)g_h4 : in_ext;
    float*       acc = acc_is_h ? (float*)g_h4       : acc_ext;
    float*       xw  = (float*)g_xw4;

    __shared__ float sW[64 * 64];
    __shared__ float sx[64][66];

    const int tid  = threadIdx.x;
    const int row0 = blockIdx.x * 64;

    for (int i = tid; i < 64 * 64; i += 128) sW[i] = W[i];
    for (int i = tid; i < 64 * 64; i += 128) {
        int r = i >> 6, c = i & 63;
        int gr = row0 + r;
        float v = (gr < n) ? in[(size_t)gr * 64 + c] : 0.0f;
        if (relu) v = fmaxf(v, 0.0f);
        sx[r][c] = v;
    }
    __syncthreads();

    const int tx = tid & 7;        // col group (8 cols = 4 pairs)
    const int ty = tid >> 3;       // row group (4 rows)
    const int c0 = tx * 8;
    const int r0 = ty * 4;

    ull a2[4][4];                  // [row][colpair] packed 2 x f32
    #pragma unroll
    for (int i = 0; i < 4; i++)
        #pragma unroll
        for (int j = 0; j < 4; j++) a2[i][j] = 0ull;

    #pragma unroll 4
    for (int k = 0; k < 64; k += 2) {
        const ull* wp0 = (const ull*)&sW[k * 64 + c0];
        const ull* wp1 = (const ull*)&sW[(k + 1) * 64 + c0];
        ull w00 = wp0[0], w01 = wp0[1], w02 = wp0[2], w03 = wp0[3];
        ull w10 = wp1[0], w11 = wp1[1], w12 = wp1[2], w13 = wp1[3];
        #pragma unroll
        for (int i = 0; i < 4; i++) {
            float2 xv = *(const float2*)&sx[r0 + i][k];   // 8B-aligned (k even)
            ull xb0, xb1;
            asm("mov.b64 %0, {%1,%1};" : "=l"(xb0) : "f"(xv.x));
            asm("mov.b64 %0, {%1,%1};" : "=l"(xb1) : "f"(xv.y));
            asm("fma.rn.f32x2 %0, %1, %2, %0;" : "+l"(a2[i][0]) : "l"(xb0), "l"(w00));
            asm("fma.rn.f32x2 %0, %1, %2, %0;" : "+l"(a2[i][1]) : "l"(xb0), "l"(w01));
            asm("fma.rn.f32x2 %0, %1, %2, %0;" : "+l"(a2[i][2]) : "l"(xb0), "l"(w02));
            asm("fma.rn.f32x2 %0, %1, %2, %0;" : "+l"(a2[i][3]) : "l"(xb0), "l"(w03));
            asm("fma.rn.f32x2 %0, %1, %2, %0;" : "+l"(a2[i][0]) : "l"(xb1), "l"(w10));
            asm("fma.rn.f32x2 %0, %1, %2, %0;" : "+l"(a2[i][1]) : "l"(xb1), "l"(w11));
            asm("fma.rn.f32x2 %0, %1, %2, %0;" : "+l"(a2[i][2]) : "l"(xb1), "l"(w12));
            asm("fma.rn.f32x2 %0, %1, %2, %0;" : "+l"(a2[i][3]) : "l"(xb1), "l"(w13));
        }
    }

    float4 bb0 = *(const float4*)&b[c0];
    float4 bb1 = *(const float4*)&b[c0 + 4];

    #pragma unroll
    for (int i = 0; i < 4; i++) {
        int gr = row0 + r0 + i;
        if (gr < n) {
            float av[8];
            #pragma unroll
            for (int j = 0; j < 4; j++)
                asm("mov.b64 {%0,%1}, %2;"
                    : "=f"(av[2 * j]), "=f"(av[2 * j + 1]) : "l"(a2[i][j]));
            float dv = g_dis[gr];
            float s  = dv * dv;
            float4 v0 = make_float4(av[0], av[1], av[2], av[3]);
            float4 v1 = make_float4(av[4], av[5], av[6], av[7]);
            *(float4*)&xw[(size_t)gr * 64 + c0]     = v0;
            *(float4*)&xw[(size_t)gr * 64 + c0 + 4] = v1;
            float4 o0 = make_float4(s * v0.x + bb0.x, s * v0.y + bb0.y,
                                    s * v0.z + bb0.z, s * v0.w + bb0.w);
            float4 o1 = make_float4(s * v1.x + bb1.x, s * v1.y + bb1.y,
                                    s * v1.z + bb1.z, s * v1.w + bb1.w);
            *(float4*)&acc[(size_t)gr * 64 + c0]     = o0;
            *(float4*)&acc[(size_t)gr * 64 + c0 + 4] = o1;
        }
    }
}

// ---------------- CSR gather, 4-edge unrolled (MLP=4 per half) -------------
__global__ __launch_bounds__(256) void k_gather(
    float* __restrict__ out_ext, int out_is_h, int n)
{
    const float4* xw  = g_xw4;
    float4*       out = out_is_h ? g_h4 : (float4*)out_ext;

    int warp = (blockIdx.x * blockDim.x + threadIdx.x) >> 5;
    if (warp >= n) return;
    int lane = threadIdx.x & 31;
    int half = lane >> 4;
    int q    = lane & 15;

    int   rs   = g_rowstart[warp];
    int   re   = g_rowstart[warp + 1];
    float disd = g_dis[warp];

    size_t oidx = (size_t)warp * 16 + q;
    float4 o;
    if (half == 0) o = out[oidx];     // init = dis^2*xw + b (from GEMM)

    float4 acc = make_float4(0.f, 0.f, 0.f, 0.f);
    int j = rs + half;
    for (; j + 6 < re; j += 8) {      // 4 edges per half in flight
        int s0 = g_csr[j];
        int s1 = g_csr[j + 2];
        int s2 = g_csr[j + 4];
        int s3 = g_csr[j + 6];
        float n0 = g_dis[s0] * disd;
        float n1 = g_dis[s1] * disd;
        float n2 = g_dis[s2] * disd;
        float n3 = g_dis[s3] * disd;
        float4 v0 = xw[(size_t)s0 * 16 + q];
        float4 v1 = xw[(size_t)s1 * 16 + q];
        float4 v2 = xw[(size_t)s2 * 16 + q];
        float4 v3 = xw[(size_t)s3 * 16 + q];
        acc.x = fmaf(n0, v0.x, acc.x); acc.y = fmaf(n0, v0.y, acc.y);
        acc.z = fmaf(n0, v0.z, acc.z); acc.w = fmaf(n0, v0.w, acc.w);
        acc.x = fmaf(n1, v1.x, acc.x); acc.y = fmaf(n1, v1.y, acc.y);
        acc.z = fmaf(n1, v1.z, acc.z); acc.w = fmaf(n1, v1.w, acc.w);
        acc.x = fmaf(n2, v2.x, acc.x); acc.y = fmaf(n2, v2.y, acc.y);
        acc.z = fmaf(n2, v2.z, acc.z); acc.w = fmaf(n2, v2.w, acc.w);
        acc.x = fmaf(n3, v3.x, acc.x); acc.y = fmaf(n3, v3.y, acc.y);
        acc.z = fmaf(n3, v3.z, acc.z); acc.w = fmaf(n3, v3.w, acc.w);
    }
    for (; j < re; j += 2) {
        int   s  = g_csr[j];
        float nm = g_dis[s] * disd;
        float4 v = xw[(size_t)s * 16 + q];
        acc.x = fmaf(nm, v.x, acc.x); acc.y = fmaf(nm, v.y, acc.y);
        acc.z = fmaf(nm, v.z, acc.z); acc.w = fmaf(nm, v.w, acc.w);
    }
    acc.x += __shfl_xor_sync(0xffffffffu, acc.x, 16);
    acc.y += __shfl_xor_sync(0xffffffffu, acc.y, 16);
    acc.z += __shfl_xor_sync(0xffffffffu, acc.z, 16);
    acc.w += __shfl_xor_sync(0xffffffffu, acc.w, 16);

    if (half == 0) {
        o.x += acc.x; o.y += acc.y; o.z += acc.z; o.w += acc.w;
        out[oidx] = o;
    }
}

// ---------------- launch ----------------
extern "C" void kernel_launch(void* const* d_in, const int* in_sizes, int n_in,
                              void* d_out, int out_size)
{
    int ix = -1, iei = -1, iw1 = -1, iw2 = -1, ib1 = -1, ib2 = -1;
    for (int i = 0; i < n_in; i++) {
        int s = in_sizes[i];
        if      (s == N_NODES * FDIM) { if (ix  < 0) ix  = i; }
        else if (s == 2 * MAX_E)      { if (iei < 0) iei = i; }
        else if (s == FDIM * FDIM)    { if (iw1 < 0) iw1 = i; else if (iw2 < 0) iw2 = i; }
        else if (s == FDIM)           { if (ib1 < 0) ib1 = i; else if (ib2 < 0) ib2 = i; }
    }
    if (ix < 0 || iei < 0 || iw1 < 0 || iw2 < 0 || ib1 < 0 || ib2 < 0) {
        ix = 0; iei = 1; iw1 = 2; ib1 = 3; iw2 = 4; ib2 = 5;
    }

    const float* x   = (const float*)d_in[ix];
    const int*   ei  = (const int*)d_in[iei];
    const float* W1  = (const float*)d_in[iw1];
    const float* b1  = (const float*)d_in[ib1];
    const float* W2  = (const float*)d_in[iw2];
    const float* b2  = (const float*)d_in[ib2];
    float*       out = (float*)d_out;

    int n = in_sizes[ix] / FDIM;
    int E = in_sizes[iei] / 2;
    if (n > N_NODES) n = N_NODES;
    if (E > MAX_E)   E = MAX_E;

    const int TB = 256;
    const int nodeBlocks = (n + TB - 1) / TB;
    const int edgeBlocks = (E + TB - 1) / TB;
    const int gemmBlocks = (n + 63) / 64;
    const int nbScan     = (n + SCAN_BLK - 1) / SCAN_BLK;
    const int gthBlocks  = (n + 7) / 8;

    k_zero      <<<nodeBlocks, TB>>>(ei, n);      // launch 0
    k_hist      <<<edgeBlocks, TB>>>(ei, E, n);   // launch 1
    k_scan_block<<<nbScan, 256>>>(n);             // launch 2
    k_scan_fin  <<<nbScan, 256>>>(nbScan, n, E);  // launch 3
    k_fill      <<<edgeBlocks, TB>>>(ei, E, n);   // launch 4

    // layer 1: h = dis^2*(x@W1) + b1  (+= neighbor messages)
    k_gemm  <<<gemmBlocks, 128>>>(x, 0, W1, b1, 0, n, nullptr, 1);   // launch 5 (ncu)
    k_gather<<<gthBlocks, TB>>>(nullptr, 1, n);

    // layer 2: out = dis^2*(relu(h)@W2) + b2  (+= neighbor messages)
    k_gemm  <<<gemmBlocks, 128>>>(nullptr, 1, W2, b2, 1, n, out, 0);
    k_gather<<<gthBlocks, TB>>>(out, 0, n);
}

// round 8
// speedup vs baseline: 1.3615x; 1.0834x over previous
#include <cuda_runtime.h>
#include <cstdint>

#define N_NODES   100000
#define FDIM      64
#define MAX_E     1250000
#define SCAN_BLK  1024                 // elements per scan block (256 thr x 4)
#define MAX_SB    128                  // max scan blocks (98 used)

typedef unsigned long long ull;

// ---------------- scratch (static __device__) ----------------
__device__ float4 g_xw4[(size_t)N_NODES * 16];   // dis-premultiplied x@W rows
__device__ float4 g_h4 [(size_t)N_NODES * 16];   // layer-1 result
__device__ float  g_dis[N_NODES];
__device__ int    g_cnt[N_NODES];                // in-degree histogram (zero-invariant)
__device__ int    g_rowstart[N_NODES + 1];       // CSR row offsets
__device__ int    g_cursor[N_NODES];             // fill cursors
__device__ int    g_csr[MAX_E];                  // CSR src indices
__device__ int    g_flag[MAX_SB];                // lookback flags (zero-invariant)

// ---------------- per-block dtype probe ----------------
__device__ __forceinline__ int probe_is64(const int* ei32, int* sflag) {
    if (threadIdx.x == 0) {
        int allz = 1;
        #pragma unroll
        for (int k = 0; k < 64; k++)
            if (ei32[2 * k + 1] != 0) { allz = 0; break; }
        *sflag = allz;
    }
    __syncthreads();
    return *sflag;
}

// ---------------- histogram of dst ----------------
__global__ void k_hist(const int* __restrict__ ei32, int E, int n) {
    __shared__ int sis64;
    int is64 = probe_is64(ei32, &sis64);
    int e = blockIdx.x * blockDim.x + threadIdx.x;
    if (e < E) {
        int d;
        if (is64) d = (int)((const long long*)ei32)[(size_t)E + e];
        else      d = ei32[(size_t)E + e];
        d = d < 0 ? 0 : (d >= n ? n - 1 : d);
        atomicAdd(&g_cnt[d], 1);
    }
}

// ------ single-pass scan (decoupled lookback): dis + rowstart + cursor -----
__global__ __launch_bounds__(256) void k_scan(int n, int E) {
    __shared__ int s[256];
    __shared__ int sbase;
    const int t   = threadIdx.x;
    const int bid = blockIdx.x;
    const int i0  = bid * SCAN_BLK + t * 4;

    int c[4];
    int sum = 0;
    #pragma unroll
    for (int k = 0; k < 4; k++) {
        int i = i0 + k;
        c[k] = (i < n) ? g_cnt[i] : 0;
        sum += c[k];
        if (i < n) g_dis[i] = rsqrtf((float)c[k] + 1.0f);   // +1 self-loop
    }

    // inclusive scan over thread sums (Hillis-Steele)
    s[t] = sum;
    __syncthreads();
    for (int off = 1; off < 256; off <<= 1) {
        int a = (t >= off) ? s[t - off] : 0;
        __syncthreads();
        s[t] += a;
        __syncthreads();
    }
    int myIncl = s[t];
    int total  = s[255];

    // publish own aggregate (value+1; 0 = unpublished)
    if (t == 0) atomicExch(&g_flag[bid], total + 1);

    // lookback: sum aggregates of all earlier blocks (all resident: 98 <= 148)
    int part = 0;
    if (t < bid) {
        int v;
        do { v = atomicAdd(&g_flag[t], 0); } while (v == 0);
        part = v - 1;
    }
    __syncthreads();               // s[] free for reuse
    s[t] = part;
    __syncthreads();
    for (int off = 128; off > 0; off >>= 1) {
        if (t < off) s[t] += s[t + off];
        __syncthreads();
    }
    if (t == 0) {
        sbase = s[0];
        if (bid == 0) g_rowstart[n] = E;
    }
    __syncthreads();

    int base = sbase + myIncl - sum;     // exclusive offset for this thread
    #pragma unroll
    for (int k = 0; k < 4; k++) {
        int i = i0 + k;
        if (i < n) {
            g_rowstart[i] = base;
            g_cursor[i]   = base;
            base += c[k];
        }
    }
}

// -------- CSR fill + reset zero-invariants (cnt, flags) for next replay ----
__global__ void k_fill(const int* __restrict__ ei32, int E, int n) {
    __shared__ int sis64;
    int is64 = probe_is64(ei32, &sis64);
    int e = blockIdx.x * blockDim.x + threadIdx.x;
    if (e < E) {
        int s, d;
        if (is64) {
            const long long* ei64 = (const long long*)ei32;
            s = (int)ei64[e];
            d = (int)ei64[(size_t)E + e];
        } else {
            s = ei32[e];
            d = ei32[(size_t)E + e];
        }
        s = s < 0 ? 0 : (s >= n ? n - 1 : s);
        d = d < 0 ? 0 : (d >= n ? n - 1 : d);
        int pos = atomicAdd(&g_cursor[d], 1);
        g_csr[pos] = s;
        g_cnt[d]   = 0;            // restore zero-invariant (racy same-value OK)
    }
    if (e < MAX_SB) g_flag[e] = 0; // reset lookback flags
}

// ---------------- GEMM (packed f32x2, k-paired): xw = dis*( (relu?)in @ W )-
__global__ __launch_bounds__(128) void k_gemm(
    const float* __restrict__ in_ext, int in_is_h,
    const float* __restrict__ W, int relu, int n)
{
    const float* in = in_is_h ? (const float*)g_h4 : in_ext;
    float*       xw = (float*)g_xw4;

    __shared__ float sW[64 * 64];
    __shared__ float sx[64][66];

    const int tid  = threadIdx.x;
    const int row0 = blockIdx.x * 64;

    for (int i = tid; i < 64 * 64; i += 128) sW[i] = W[i];
    for (int i = tid; i < 64 * 64; i += 128) {
        int r = i >> 6, c = i & 63;
        int gr = row0 + r;
        float v = (gr < n) ? in[(size_t)gr * 64 + c] : 0.0f;
        if (relu) v = fmaxf(v, 0.0f);
        sx[r][c] = v;
    }
    __syncthreads();

    const int tx = tid & 7;        // col group (8 cols = 4 pairs)
    const int ty = tid >> 3;       // row group (4 rows)
    const int c0 = tx * 8;
    const int r0 = ty * 4;

    ull a2[4][4];
    #pragma unroll
    for (int i = 0; i < 4; i++)
        #pragma unroll
        for (int j = 0; j < 4; j++) a2[i][j] = 0ull;

    #pragma unroll 4
    for (int k = 0; k < 64; k += 2) {
        const ull* wp0 = (const ull*)&sW[k * 64 + c0];
        const ull* wp1 = (const ull*)&sW[(k + 1) * 64 + c0];
        ull w00 = wp0[0], w01 = wp0[1], w02 = wp0[2], w03 = wp0[3];
        ull w10 = wp1[0], w11 = wp1[1], w12 = wp1[2], w13 = wp1[3];
        #pragma unroll
        for (int i = 0; i < 4; i++) {
            float2 xv = *(const float2*)&sx[r0 + i][k];
            ull xb0, xb1;
            asm("mov.b64 %0, {%1,%1};" : "=l"(xb0) : "f"(xv.x));
            asm("mov.b64 %0, {%1,%1};" : "=l"(xb1) : "f"(xv.y));
            asm("fma.rn.f32x2 %0, %1, %2, %0;" : "+l"(a2[i][0]) : "l"(xb0), "l"(w00));
            asm("fma.rn.f32x2 %0, %1, %2, %0;" : "+l"(a2[i][1]) : "l"(xb0), "l"(w01));
            asm("fma.rn.f32x2 %0, %1, %2, %0;" : "+l"(a2[i][2]) : "l"(xb0), "l"(w02));
            asm("fma.rn.f32x2 %0, %1, %2, %0;" : "+l"(a2[i][3]) : "l"(xb0), "l"(w03));
            asm("fma.rn.f32x2 %0, %1, %2, %0;" : "+l"(a2[i][0]) : "l"(xb1), "l"(w10));
            asm("fma.rn.f32x2 %0, %1, %2, %0;" : "+l"(a2[i][1]) : "l"(xb1), "l"(w11));
            asm("fma.rn.f32x2 %0, %1, %2, %0;" : "+l"(a2[i][2]) : "l"(xb1), "l"(w12));
            asm("fma.rn.f32x2 %0, %1, %2, %0;" : "+l"(a2[i][3]) : "l"(xb1), "l"(w13));
        }
    }

    #pragma unroll
    for (int i = 0; i < 4; i++) {
        int gr = row0 + r0 + i;
        if (gr < n) {
            float av[8];
            #pragma unroll
            for (int j = 0; j < 4; j++)
                asm("mov.b64 {%0,%1}, %2;"
                    : "=f"(av[2 * j]), "=f"(av[2 * j + 1]) : "l"(a2[i][j]));
            float dv = g_dis[gr];
            float4 v0 = make_float4(dv * av[0], dv * av[1], dv * av[2], dv * av[3]);
            float4 v1 = make_float4(dv * av[4], dv * av[5], dv * av[6], dv * av[7]);
            *(float4*)&xw[(size_t)gr * 64 + c0]     = v0;
            *(float4*)&xw[(size_t)gr * 64 + c0 + 4] = v1;
        }
    }
}

// ------- CSR gather: out[d] = dis[d]*(row[d] + sum rows[s_j]) + b ----------
// warp per dst node; halves process alternating edges; lane owns one float4.
__global__ __launch_bounds__(256) void k_gather(
    const float* __restrict__ bias,
    float* __restrict__ out_ext, int out_is_h, int n)
{
    const float4* xw  = g_xw4;
    float4*       out = out_is_h ? g_h4 : (float4*)out_ext;

    int warp = (blockIdx.x * blockDim.x + threadIdx.x) >> 5;
    if (warp >= n) return;
    int lane = threadIdx.x & 31;
    int half = lane >> 4;
    int q    = lane & 15;

    int   rs   = g_rowstart[warp];
    int   re   = g_rowstart[warp + 1];
    float disd = g_dis[warp];

    float4 acc = make_float4(0.f, 0.f, 0.f, 0.f);
    if (half == 0) acc = xw[(size_t)warp * 16 + q];   // self row (premult by dis)

    int j = rs + half;
    for (; j + 6 < re; j += 8) {        // 4 rows per half in flight (MLP=4)
        int s0 = g_csr[j];
        int s1 = g_csr[j + 2];
        int s2 = g_csr[j + 4];
        int s3 = g_csr[j + 6];
        float4 v0 = xw[(size_t)s0 * 16 + q];
        float4 v1 = xw[(size_t)s1 * 16 + q];
        float4 v2 = xw[(size_t)s2 * 16 + q];
        float4 v3 = xw[(size_t)s3 * 16 + q];
        acc.x += v0.x + v1.x; acc.y += v0.y + v1.y;
        acc.z += v0.z + v1.z; acc.w += v0.w + v1.w;
        acc.x += v2.x + v3.x; acc.y += v2.y + v3.y;
        acc.z += v2.z + v3.z; acc.w += v2.w + v3.w;
    }
    for (; j < re; j += 2) {
        float4 v = xw[(size_t)g_csr[j] * 16 + q];
        acc.x += v.x; acc.y += v.y; acc.z += v.z; acc.w += v.w;
    }
    acc.x += __shfl_xor_sync(0xffffffffu, acc.x, 16);
    acc.y += __shfl_xor_sync(0xffffffffu, acc.y, 16);
    acc.z += __shfl_xor_sync(0xffffffffu, acc.z, 16);
    acc.w += __shfl_xor_sync(0xffffffffu, acc.w, 16);

    if (half == 0) {
        float4 bb = ((const float4*)bias)[q];
        out[(size_t)warp * 16 + q] =
            make_float4(fmaf(disd, acc.x, bb.x), fmaf(disd, acc.y, bb.y),
                        fmaf(disd, acc.z, bb.z), fmaf(disd, acc.w, bb.w));
    }
}

// ---------------- launch ----------------
extern "C" void kernel_launch(void* const* d_in, const int* in_sizes, int n_in,
                              void* d_out, int out_size)
{
    int ix = -1, iei = -1, iw1 = -1, iw2 = -1, ib1 = -1, ib2 = -1;
    for (int i = 0; i < n_in; i++) {
        int s = in_sizes[i];
        if      (s == N_NODES * FDIM) { if (ix  < 0) ix  = i; }
        else if (s == 2 * MAX_E)      { if (iei < 0) iei = i; }
        else if (s == FDIM * FDIM)    { if (iw1 < 0) iw1 = i; else if (iw2 < 0) iw2 = i; }
        else if (s == FDIM)           { if (ib1 < 0) ib1 = i; else if (ib2 < 0) ib2 = i; }
    }
    if (ix < 0 || iei < 0 || iw1 < 0 || iw2 < 0 || ib1 < 0 || ib2 < 0) {
        ix = 0; iei = 1; iw1 = 2; ib1 = 3; iw2 = 4; ib2 = 5;
    }

    const float* x   = (const float*)d_in[ix];
    const int*   ei  = (const int*)d_in[iei];
    const float* W1  = (const float*)d_in[iw1];
    const float* b1  = (const float*)d_in[ib1];
    const float* W2  = (const float*)d_in[iw2];
    const float* b2  = (const float*)d_in[ib2];
    float*       out = (float*)d_out;

    int n = in_sizes[ix] / FDIM;
    int E = in_sizes[iei] / 2;
    if (n > N_NODES) n = N_NODES;
    if (E > MAX_E)   E = MAX_E;

    const int TB = 256;
    const int edgeBlocks = (E + TB - 1) / TB;
    const int gemmBlocks = (n + 63) / 64;
    const int nbScan     = (n + SCAN_BLK - 1) / SCAN_BLK;   // 98 (<= 148 SMs)
    const int gthBlocks  = (n + 7) / 8;

    k_hist<<<edgeBlocks, TB>>>(ei, E, n);                  // launch 0
    k_scan<<<nbScan, 256>>>(n, E);                         // launch 1
    k_fill<<<edgeBlocks, TB>>>(ei, E, n);                  // launch 2

    // layer 1: h = dis*(self + sum rows) + b1, rows = dis*(x@W1)
    k_gemm  <<<gemmBlocks, 128>>>(x, 0, W1, 0, n);         // launch 3
    k_gather<<<gthBlocks, TB>>>(b1, nullptr, 1, n);        // launch 4

    // layer 2: out = dis*(self + sum rows) + b2, rows = dis*(relu(h)@W2)
    k_gemm  <<<gemmBlocks, 128>>>(nullptr, 1, W2, 1, n);   // launch 5 (ncu window)
    k_gather<<<gthBlocks, TB>>>(b2, out, 0, n);            // launch 6
}

// round 9
// speedup vs baseline: 1.4318x; 1.0517x over previous
#include <cuda_runtime.h>
#include <cstdint>

#define N_NODES   100000
#define FDIM      64
#define MAX_E     1250000
#define SCAN_BLK  1024                 // elements per scan block (256 thr x 4)
#define MAX_SB    128                  // max scan blocks (98 used)

typedef unsigned long long ull;

// ---------------- scratch (static __device__) ----------------
__device__ float4 g_xw4[(size_t)N_NODES * 16];   // dis-premultiplied x@W rows
__device__ float4 g_h4 [(size_t)N_NODES * 16];   // layer-1 result
__device__ float  g_dis[N_NODES];
__device__ int    g_cnt[N_NODES];                // in-degree histogram (zero-invariant)
__device__ int    g_rowstart[N_NODES + 1];       // CSR row offsets
__device__ int    g_cursor[N_NODES];             // fill cursors
__device__ int    g_csr[MAX_E];                  // CSR src indices
__device__ int    g_flag[MAX_SB];                // lookback flags (zero-invariant)

// ---------------- per-block dtype probe ----------------
__device__ __forceinline__ int probe_is64(const int* ei32, int* sflag) {
    if (threadIdx.x == 0) {
        int allz = 1;
        #pragma unroll
        for (int k = 0; k < 64; k++)
            if (ei32[2 * k + 1] != 0) { allz = 0; break; }
        *sflag = allz;
    }
    __syncthreads();
    return *sflag;
}

// ---------------- histogram of dst ----------------
__global__ void k_hist(const int* __restrict__ ei32, int E, int n) {
    __shared__ int sis64;
    int is64 = probe_is64(ei32, &sis64);
    int e = blockIdx.x * blockDim.x + threadIdx.x;
    if (e < E) {
        int d;
        if (is64) d = (int)((const long long*)ei32)[(size_t)E + e];
        else      d = ei32[(size_t)E + e];
        d = d < 0 ? 0 : (d >= n ? n - 1 : d);
        atomicAdd(&g_cnt[d], 1);
    }
}

// ------ single-pass scan (decoupled lookback): dis + rowstart + cursor -----
__global__ __launch_bounds__(256) void k_scan(int n, int E) {
    __shared__ int s[256];
    __shared__ int sbase;
    const int t   = threadIdx.x;
    const int bid = blockIdx.x;
    const int i0  = bid * SCAN_BLK + t * 4;

    int c[4];
    int sum = 0;
    #pragma unroll
    for (int k = 0; k < 4; k++) {
        int i = i0 + k;
        c[k] = (i < n) ? g_cnt[i] : 0;
        sum += c[k];
        if (i < n) g_dis[i] = rsqrtf((float)c[k] + 1.0f);   // +1 self-loop
    }

    s[t] = sum;
    __syncthreads();
    for (int off = 1; off < 256; off <<= 1) {
        int a = (t >= off) ? s[t - off] : 0;
        __syncthreads();
        s[t] += a;
        __syncthreads();
    }
    int myIncl = s[t];
    int total  = s[255];

    if (t == 0) atomicExch(&g_flag[bid], total + 1);

    int part = 0;
    if (t < bid) {
        int v;
        do { v = atomicAdd(&g_flag[t], 0); } while (v == 0);
        part = v - 1;
    }
    __syncthreads();
    s[t] = part;
    __syncthreads();
    for (int off = 128; off > 0; off >>= 1) {
        if (t < off) s[t] += s[t + off];
        __syncthreads();
    }
    if (t == 0) {
        sbase = s[0];
        if (bid == 0) g_rowstart[n] = E;
    }
    __syncthreads();

    int base = sbase + myIncl - sum;
    #pragma unroll
    for (int k = 0; k < 4; k++) {
        int i = i0 + k;
        if (i < n) {
            g_rowstart[i] = base;
            g_cursor[i]   = base;
            base += c[k];
        }
    }
}

// -------- CSR fill + reset zero-invariants (cnt, flags) for next replay ----
__global__ void k_fill(const int* __restrict__ ei32, int E, int n) {
    __shared__ int sis64;
    int is64 = probe_is64(ei32, &sis64);
    int e = blockIdx.x * blockDim.x + threadIdx.x;
    if (e < E) {
        int s, d;
        if (is64) {
            const long long* ei64 = (const long long*)ei32;
            s = (int)ei64[e];
            d = (int)ei64[(size_t)E + e];
        } else {
            s = ei32[e];
            d = ei32[(size_t)E + e];
        }
        s = s < 0 ? 0 : (s >= n ? n - 1 : s);
        d = d < 0 ? 0 : (d >= n ? n - 1 : d);
        int pos = atomicAdd(&g_cursor[d], 1);
        g_csr[pos] = s;
        g_cnt[d]   = 0;
    }
    if (e < MAX_SB) g_flag[e] = 0;
}

// -------- GEMM (f32x2, 8x8 per-thread tile, interleaved rows) --------------
// block: 128 threads, tile 128 rows x 64 cols. thread = rows {ty+16i} x 8 cols.
__global__ __launch_bounds__(128, 4) void k_gemm(
    const float* __restrict__ in_ext, int in_is_h,
    const float* __restrict__ W, int relu, int n)
{
    const float* in = in_is_h ? (const float*)g_h4 : in_ext;
    float*       xw = (float*)g_xw4;

    __shared__ float sW[64 * 64];
    __shared__ float sx[128][66];   // row stride 66: ty-adjacent rows hit banks +2

    const int tid  = threadIdx.x;
    const int row0 = blockIdx.x * 128;

    // fill W (float4)
    {
        const float4* W4  = (const float4*)W;
        float4*       sW4 = (float4*)sW;
        #pragma unroll
        for (int i = 0; i < 8; i++) sW4[tid + i * 128] = W4[tid + i * 128];
    }
    // fill x: float4 global loads, float2 smem stores (pad 66 => 8B-aligned)
    for (int idx = tid; idx < 128 * 16; idx += 128) {
        int r  = idx >> 4;
        int c4 = (idx & 15) * 4;
        int gr = row0 + r;
        float4 v = make_float4(0.f, 0.f, 0.f, 0.f);
        if (gr < n) v = *(const float4*)&in[(size_t)gr * 64 + c4];
        if (relu) {
            v.x = fmaxf(v.x, 0.f); v.y = fmaxf(v.y, 0.f);
            v.z = fmaxf(v.z, 0.f); v.w = fmaxf(v.w, 0.f);
        }
        *(float2*)&sx[r][c4]     = make_float2(v.x, v.y);
        *(float2*)&sx[r][c4 + 2] = make_float2(v.z, v.w);
    }
    __syncthreads();

    const int tx = tid & 7;        // col group: 8 cols = 4 pairs
    const int ty = tid >> 3;       // 16 row groups; rows ty, ty+16, ..., ty+112
    const int c0 = tx * 8;

    ull a2[8][4];
    #pragma unroll
    for (int i = 0; i < 8; i++)
        #pragma unroll
        for (int j = 0; j < 4; j++) a2[i][j] = 0ull;

    #pragma unroll 2
    for (int k = 0; k < 64; k += 2) {
        const ull* wp0 = (const ull*)&sW[k * 64 + c0];
        const ull* wp1 = (const ull*)&sW[(k + 1) * 64 + c0];
        ull w00 = wp0[0], w01 = wp0[1], w02 = wp0[2], w03 = wp0[3];
        ull w10 = wp1[0], w11 = wp1[1], w12 = wp1[2], w13 = wp1[3];
        #pragma unroll
        for (int i = 0; i < 8; i++) {
            float2 xv = *(const float2*)&sx[ty + (i << 4)][k];
            ull xb0, xb1;
            asm("mov.b64 %0, {%1,%1};" : "=l"(xb0) : "f"(xv.x));
            asm("mov.b64 %0, {%1,%1};" : "=l"(xb1) : "f"(xv.y));
            asm("fma.rn.f32x2 %0, %1, %2, %0;" : "+l"(a2[i][0]) : "l"(xb0), "l"(w00));
            asm("fma.rn.f32x2 %0, %1, %2, %0;" : "+l"(a2[i][1]) : "l"(xb0), "l"(w01));
            asm("fma.rn.f32x2 %0, %1, %2, %0;" : "+l"(a2[i][2]) : "l"(xb0), "l"(w02));
            asm("fma.rn.f32x2 %0, %1, %2, %0;" : "+l"(a2[i][3]) : "l"(xb0), "l"(w03));
            asm("fma.rn.f32x2 %0, %1, %2, %0;" : "+l"(a2[i][0]) : "l"(xb1), "l"(w10));
            asm("fma.rn.f32x2 %0, %1, %2, %0;" : "+l"(a2[i][1]) : "l"(xb1), "l"(w11));
            asm("fma.rn.f32x2 %0, %1, %2, %0;" : "+l"(a2[i][2]) : "l"(xb1), "l"(w12));
            asm("fma.rn.f32x2 %0, %1, %2, %0;" : "+l"(a2[i][3]) : "l"(xb1), "l"(w13));
        }
    }

    #pragma unroll
    for (int i = 0; i < 8; i++) {
        int gr = row0 + ty + (i << 4);
        if (gr < n) {
            float av[8];
            #pragma unroll
            for (int j = 0; j < 4; j++)
                asm("mov.b64 {%0,%1}, %2;"
                    : "=f"(av[2 * j]), "=f"(av[2 * j + 1]) : "l"(a2[i][j]));
            float dv = g_dis[gr];
            float4 v0 = make_float4(dv * av[0], dv * av[1], dv * av[2], dv * av[3]);
            float4 v1 = make_float4(dv * av[4], dv * av[5], dv * av[6], dv * av[7]);
            *(float4*)&xw[(size_t)gr * 64 + c0]     = v0;
            *(float4*)&xw[(size_t)gr * 64 + c0 + 4] = v1;
        }
    }
}

// ------- CSR gather: out[d] = dis[d]*(row[d] + sum rows[s_j]) + b ----------
__global__ __launch_bounds__(256) void k_gather(
    const float* __restrict__ bias,
    float* __restrict__ out_ext, int out_is_h, int n)
{
    const float4* xw  = g_xw4;
    float4*       out = out_is_h ? g_h4 : (float4*)out_ext;

    int warp = (blockIdx.x * blockDim.x + threadIdx.x) >> 5;
    if (warp >= n) return;
    int lane = threadIdx.x & 31;
    int half = lane >> 4;
    int q    = lane & 15;

    int   rs   = g_rowstart[warp];
    int   re   = g_rowstart[warp + 1];
    float disd = g_dis[warp];

    float4 acc = make_float4(0.f, 0.f, 0.f, 0.f);
    if (half == 0) acc = xw[(size_t)warp * 16 + q];   // self row

    int j = rs + half;
    for (; j + 6 < re; j += 8) {
        int s0 = g_csr[j];
        int s1 = g_csr[j + 2];
        int s2 = g_csr[j + 4];
        int s3 = g_csr[j + 6];
        float4 v0 = xw[(size_t)s0 * 16 + q];
        float4 v1 = xw[(size_t)s1 * 16 + q];
        float4 v2 = xw[(size_t)s2 * 16 + q];
        float4 v3 = xw[(size_t)s3 * 16 + q];
        acc.x += v0.x + v1.x; acc.y += v0.y + v1.y;
        acc.z += v0.z + v1.z; acc.w += v0.w + v1.w;
        acc.x += v2.x + v3.x; acc.y += v2.y + v3.y;
        acc.z += v2.z + v3.z; acc.w += v2.w + v3.w;
    }
    for (; j < re; j += 2) {
        float4 v = xw[(size_t)g_csr[j] * 16 + q];
        acc.x += v.x; acc.y += v.y; acc.z += v.z; acc.w += v.w;
    }
    acc.x += __shfl_xor_sync(0xffffffffu, acc.x, 16);
    acc.y += __shfl_xor_sync(0xffffffffu, acc.y, 16);
    acc.z += __shfl_xor_sync(0xffffffffu, acc.z, 16);
    acc.w += __shfl_xor_sync(0xffffffffu, acc.w, 16);

    if (half == 0) {
        float4 bb = ((const float4*)bias)[q];
        out[(size_t)warp * 16 + q] =
            make_float4(fmaf(disd, acc.x, bb.x), fmaf(disd, acc.y, bb.y),
                        fmaf(disd, acc.z, bb.z), fmaf(disd, acc.w, bb.w));
    }
}

// ---------------- launch ----------------
extern "C" void kernel_launch(void* const* d_in, const int* in_sizes, int n_in,
                              void* d_out, int out_size)
{
    int ix = -1, iei = -1, iw1 = -1, iw2 = -1, ib1 = -1, ib2 = -1;
    for (int i = 0; i < n_in; i++) {
        int s = in_sizes[i];
        if      (s == N_NODES * FDIM) { if (ix  < 0) ix  = i; }
        else if (s == 2 * MAX_E)      { if (iei < 0) iei = i; }
        else if (s == FDIM * FDIM)    { if (iw1 < 0) iw1 = i; else if (iw2 < 0) iw2 = i; }
        else if (s == FDIM)           { if (ib1 < 0) ib1 = i; else if (ib2 < 0) ib2 = i; }
    }
    if (ix < 0 || iei < 0 || iw1 < 0 || iw2 < 0 || ib1 < 0 || ib2 < 0) {
        ix = 0; iei = 1; iw1 = 2; ib1 = 3; iw2 = 4; ib2 = 5;
    }

    const float* x   = (const float*)d_in[ix];
    const int*   ei  = (const int*)d_in[iei];
    const float* W1  = (const float*)d_in[iw1];
    const float* b1  = (const float*)d_in[ib1];
    const float* W2  = (const float*)d_in[iw2];
    const float* b2  = (const float*)d_in[ib2];
    float*       out = (float*)d_out;

    int n = in_sizes[ix] / FDIM;
    int E = in_sizes[iei] / 2;
    if (n > N_NODES) n = N_NODES;
    if (E > MAX_E)   E = MAX_E;

    const int TB = 256;
    const int edgeBlocks = (E + TB - 1) / TB;
    const int gemmBlocks = (n + 127) / 128;
    const int nbScan     = (n + SCAN_BLK - 1) / SCAN_BLK;   // 98 (<= 148 SMs)
    const int gthBlocks  = (n + 7) / 8;

    k_hist<<<edgeBlocks, TB>>>(ei, E, n);                  // launch 0
    k_scan<<<nbScan, 256>>>(n, E);                         // launch 1
    k_fill<<<edgeBlocks, TB>>>(ei, E, n);                  // launch 2

    // layer 1: h = dis*(self + sum rows) + b1, rows = dis*(x@W1)
    k_gemm  <<<gemmBlocks, 128>>>(x, 0, W1, 0, n);         // launch 3
    k_gather<<<gthBlocks, TB>>>(b1, nullptr, 1, n);        // launch 4

    // layer 2: out = dis*(self + sum rows) + b2, rows = dis*(relu(h)@W2)
    k_gemm  <<<gemmBlocks, 128>>>(nullptr, 1, W2, 1, n);   // launch 5 (ncu window)
    k_gather<<<gthBlocks, TB>>>(b2, out, 0, n);            // launch 6
}